// round 16
// baseline (speedup 1.0000x reference)
#include <cuda_runtime.h>
#include <math.h>

#define BB 2
#define SS 128
#define HH 256
#define CC 8
#define PAD 260        // main-kernel smem row stride (floats, multiple of 4)

// ---------------- scratch (device globals; no allocation allowed) ----------
__device__ float g_scorep[256 * 64];           // 64 KB  [bidA][c*8+sl]
__device__ float g_cumexp[BB * SS * CC];       // 8 KB   [b][s][c]
__device__ float g_cumm[BB * SS * CC * HH];    // 2 MB   [b][s][c][h]

// ---------------- packed f32x2 helpers (sm_100a) ---------------------------
// NOTE: only add/mul/fma exist in the f32x2 SIMD set; max.f32x2 does NOT
// (ptxas round-14 failure). relu stays scalar FMNMX.
union F2U { float2 f; unsigned long long u; };

__device__ __forceinline__ void pk_add(F2U& d, const F2U& a, const F2U& b) {
    asm("add.rn.f32x2 %0, %1, %2;" : "=l"(d.u) : "l"(a.u), "l"(b.u));
}
__device__ __forceinline__ void pk_fma(F2U& d, const F2U& a, const F2U& b,
                                       const F2U& c) {
    asm("fma.rn.f32x2 %0, %1, %2, %3;" : "=l"(d.u) : "l"(a.u), "l"(b.u), "l"(c.u));
}

// ---------------------------------------------------------------------------
// Kernel A: z = relu(memory . W^T + Wb) kept ON-CHIP; emits partial scores
//   g_scorep[bid][c*8+sl] = sum_{h in tile} U[c,h] * z[s0+sl, h]
// grid 256 = (32 s-tiles of 8 rows) x (8 h-tiles of 32); 256 threads.
// W LDGs hoisted to kernel start: their cold latency overlaps Msh staging +
// barrier instead of heading the FMA phase. Score tail uses all 256 threads.
// ---------------------------------------------------------------------------
__global__ void __launch_bounds__(256, 2) kernelA(const float* __restrict__ memory,
                                                  const float* __restrict__ Ww,
                                                  const float* __restrict__ Wb,
                                                  const float* __restrict__ Uw)
{
    __shared__ float Msh[8 * HH];    // 8 KB
    __shared__ float zsh[8][36];     // 8 s-rows x 32 h (pad 36: float4-clean)

    int bid = blockIdx.x;
    int st = bid >> 3;               // s-tile 0..31
    int ht = bid & 7;                // h-tile 0..7
    int s0 = st * 8;
    int tid = threadIdx.x;
    int lane = tid & 31, w = tid >> 5;

    int hl = lane >> 3;              // 0..3
    int kp = lane & 7;               // 0..7
    int h = ht * 32 + w * 4 + hl;

    // W prefetch FIRST — latency hidden behind staging + barrier
    float4 wv[8];
    const float4* wr = (const float4*)&Ww[h * HH];
#pragma unroll
    for (int i = 0; i < 8; i++) wv[i] = wr[i * 8 + kp];
    float bias = Wb[h];

    // stage 8 memory rows (512 float4, 2 per thread)
#pragma unroll
    for (int t = 0; t < 2; t++) {
        int idx = tid + t * 256;
        int rr = idx >> 6;
        int k4 = idx & 63;
        ((float4*)&Msh[rr * HH])[k4] =
            ((const float4*)&memory[(s0 + rr) * HH])[k4];
    }
    __syncthreads();

    float acc[8];
#pragma unroll
    for (int r = 0; r < 8; r++) acc[r] = 0.0f;

#pragma unroll
    for (int i = 0; i < 8; i++) {
#pragma unroll
        for (int r = 0; r < 8; r++) {
            float4 m = *(const float4*)&Msh[r * HH + i * 32 + kp * 4];
            acc[r] = fmaf(m.x, wv[i].x,
                     fmaf(m.y, wv[i].y,
                     fmaf(m.z, wv[i].z,
                     fmaf(m.w, wv[i].w, acc[r]))));
        }
    }

#pragma unroll
    for (int r = 0; r < 8; r++) {
        float v = acc[r];
        v += __shfl_xor_sync(0xffffffffu, v, 1);
        v += __shfl_xor_sync(0xffffffffu, v, 2);
        v += __shfl_xor_sync(0xffffffffu, v, 4);
        acc[r] = v;
    }
    if (kp == 0) {
#pragma unroll
        for (int r = 0; r < 8; r++)
            zsh[r][w * 4 + hl] = fmaxf(acc[r] + bias, 0.0f);
    }
    __syncthreads();

    // partial scores, ALL 256 threads: warp = c, lane = sl*4 + kq.
    // Each thread: 8-float dot over h-chunk kq*8..kq*8+7; shfl-reduce over kq.
    {
        int c  = w;                  // 0..7
        int sl = lane >> 2;          // 0..7
        int kq = lane & 3;           // 0..3
        const float4* ur = (const float4*)(Uw + c * HH + ht * 32);
        float p = 0.0f;
#pragma unroll
        for (int k = 0; k < 2; k++) {
            float4 u = ur[kq * 2 + k];
            const float* zp = &zsh[sl][kq * 8 + k * 4];
            float4 zv = *(const float4*)zp;
            p += u.x * zv.x + u.y * zv.y + u.z * zv.z + u.w * zv.w;
        }
        p += __shfl_xor_sync(0xffffffffu, p, 1);
        p += __shfl_xor_sync(0xffffffffu, p, 2);
        if (kq == 0)
            g_scorep[bid * 64 + c * 8 + sl] = p;
    }
}

// ---------------------------------------------------------------------------
// Kernel B (fused B1+B2): grid 128 = (b,c) x 8 h-chunks; 256 threads.
// Phase 1 (tid<128): score[s] = sum_ht scorep (L2-hot); softmax-exp; scan.
//   cumexp stored by hc==0 blocks only.
// Phase 2 (all 256): cumm for 32 h-lanes x 8 s-groups of 16.
// ---------------------------------------------------------------------------
__global__ void __launch_bounds__(256) kernelB(const float* __restrict__ memory)
{
    __shared__ float esh[SS];
    __shared__ float wred[4];
    __shared__ float wsum[4];
    __shared__ float psum[8][32];

    int bid = blockIdx.x;
    int hc = bid & 7;
    int bc = bid >> 3;               // b*CC + c
    int b = bc >> 3;
    int c = bc & 7;
    int tid = threadIdx.x;
    int lane = tid & 31, w = tid >> 5;

    // Phase 1a: score + warp max (warps 0..3)
    float sc = 0.0f;
    if (tid < SS) {
        int grow = b * SS + tid;
        int st = grow >> 3, sl = grow & 7;
#pragma unroll
        for (int ht = 0; ht < 8; ht++)
            sc += g_scorep[(st * 8 + ht) * 64 + c * 8 + sl];
        float m = sc;
#pragma unroll
        for (int o = 16; o > 0; o >>= 1)
            m = fmaxf(m, __shfl_xor_sync(0xffffffffu, m, o));
        if (lane == 0) wred[w] = m;
    }
    __syncthreads();

    // Phase 1b: exp + warp scan; e -> esh
    float x = 0.0f;
    if (tid < SS) {
        float mx = fmaxf(fmaxf(wred[0], wred[1]), fmaxf(wred[2], wred[3]));
        float e = expf(sc - mx);
        x = e;
#pragma unroll
        for (int o = 1; o < 32; o <<= 1) {
            float t = __shfl_up_sync(0xffffffffu, x, o);
            if (lane >= o) x += t;
        }
        if (lane == 31) wsum[w] = x;
        esh[tid] = e;
    }
    __syncthreads();

    // Phase 1c: cumexp store (hc==0 blocks only)
    if (hc == 0 && tid < SS) {
        float pre = 0.0f;
        for (int ww = 0; ww < w; ww++) pre += wsum[ww];
        g_cumexp[(b * SS + tid) * CC + c] = x + pre;
    }

    // Phase 2: cumm
    {
        int hl = tid & 31;
        int sg = tid >> 5;           // s-group 0..7
        int h = hc * 32 + hl;
        const float* mp = memory + (size_t)b * SS * HH + h;

        float val[16];
        float run = 0.0f;
#pragma unroll
        for (int k = 0; k < 16; k++) {
            int s = sg * 16 + k;
            run = fmaf(mp[(size_t)s * HH], esh[s], run);
            val[k] = run;
        }
        psum[sg][hl] = run;
        __syncthreads();

        float off = 0.0f;
        for (int t = 0; t < sg; t++) off += psum[t][hl];

        float* op = g_cumm + ((size_t)b * SS * CC + c) * HH + h;
#pragma unroll
        for (int k = 0; k < 16; k++) {
            int s = sg * 16 + k;
            op[(size_t)s * (CC * HH)] = val[k] + off;
        }
    }
}

// ---------------------------------------------------------------------------
// Main kernel (c-split, packed add/fma f32x2, scalar FMNMX relu):
//   out[b,i,j,c] = (sum_h relu(R[j,h] + negP[i,h]) * V[c,h]) / denom + V_b[c]
// grid 1024 = b(2) x i-tile(8 of 16) x j-tile(8 of 16) x c(8); 128 threads.
// ---------------------------------------------------------------------------
__global__ void __launch_bounds__(128, 6) kernelMain(const float* __restrict__ Vw,
                                                     const float* __restrict__ Vb,
                                                     float* __restrict__ out)
{
    __shared__ float Psh[16 * PAD];    // 4160 fl (negated P)
    __shared__ float Rsh[16 * PAD];    // 4160 fl
    __shared__ float Vsh[HH];          // 256 fl   (total 34304 B)
    float* red = Psh;                  // alias; P dead by reduction time

    int bid = blockIdx.x;
    int c  = bid & 7;
    int jt = (bid >> 3) & 7;
    int it = (bid >> 6) & 7;
    int b  = bid >> 9;
    int i0 = it * 16, j0 = jt * 16;
    int tid = threadIdx.x;

    if (tid < 64)
        ((float4*)Vsh)[tid] = ((const float4*)(Vw + c * HH))[tid];

    // stage negated-P and R tiles: 16 rows each, 8 threads/row
    {
        int rr = tid >> 3;             // 0..15
        int c8 = tid & 7;
        int gi = i0 + rr;
        int gj = j0 + rr;
        const float* srcR = &g_cumm[((size_t)(b * SS + gj) * CC + c) * HH];
        const float* srcP = (gi == 0) ? (const float*)0
            : &g_cumm[((size_t)(b * SS + gi - 1) * CC + c) * HH];
        float* dstR = &Rsh[rr * PAD];
        float* dstP = &Psh[rr * PAD];
#pragma unroll
        for (int k = 0; k < 8; k++) {
            int h = c8 * 4 + k * 32;
            *(float4*)&dstR[h] = *(const float4*)&srcR[h];
            float4 pv = srcP ? *(const float4*)&srcP[h]
                             : make_float4(0.f, 0.f, 0.f, 0.f);
            pv.x = -pv.x; pv.y = -pv.y; pv.z = -pv.z; pv.w = -pv.w;
            *(float4*)&dstP[h] = pv;
        }
    }
    __syncthreads();

    // epilogue operands loaded EARLY
    float cej[2], cei[2];
#pragma unroll
    for (int rep = 0; rep < 2; rep++) {
        int idx = tid + rep * 128;
        int gie = i0 + (idx >> 4), gje = j0 + (idx & 15);
        cej[rep] = g_cumexp[(b * SS + gje) * CC + c];
        cei[rep] = (gie > 0) ? g_cumexp[(b * SS + gie - 1) * CC + c] : 0.0f;
    }
    float vb = Vb[c];

    int lane = tid & 31;
    int hq = tid >> 5;                 // h quarter 0..3
    int ilane = lane & 7;              // 0..7  (phase-major)
    int jlane = lane >> 3;             // 0..3

    F2U acc[2][4];
#pragma unroll
    for (int ii = 0; ii < 2; ii++)
#pragma unroll
        for (int jj = 0; jj < 4; jj++) {
            acc[ii][jj].f.x = 0.0f;
            acc[ii][jj].f.y = 0.0f;
        }

    int hbase = hq * 64;
#pragma unroll 4
    for (int hh = 0; hh < 64; hh += 4) {
        int h = hbase + hh;
        float4 v  = *(const float4*)&Vsh[h];
        float4 p0 = *(const float4*)&Psh[ilane * PAD + h];
        float4 p1 = *(const float4*)&Psh[(ilane + 8) * PAD + h];
        F2U v01, v23, p0a, p0b, p1a, p1b;
        v01.f = make_float2(v.x, v.y);   v23.f = make_float2(v.z, v.w);
        p0a.f = make_float2(p0.x, p0.y); p0b.f = make_float2(p0.z, p0.w);
        p1a.f = make_float2(p1.x, p1.y); p1b.f = make_float2(p1.z, p1.w);
#pragma unroll
        for (int jj = 0; jj < 4; jj++) {
            float4 r = *(const float4*)&Rsh[(jlane + 4 * jj) * PAD + h];
            F2U r01, r23, t;
            r01.f = make_float2(r.x, r.y);
            r23.f = make_float2(r.z, r.w);
            pk_add(t, r01, p0a);
            t.f.x = fmaxf(t.f.x, 0.0f); t.f.y = fmaxf(t.f.y, 0.0f);
            pk_fma(acc[0][jj], t, v01, acc[0][jj]);
            pk_add(t, r23, p0b);
            t.f.x = fmaxf(t.f.x, 0.0f); t.f.y = fmaxf(t.f.y, 0.0f);
            pk_fma(acc[0][jj], t, v23, acc[0][jj]);
            pk_add(t, r01, p1a);
            t.f.x = fmaxf(t.f.x, 0.0f); t.f.y = fmaxf(t.f.y, 0.0f);
            pk_fma(acc[1][jj], t, v01, acc[1][jj]);
            pk_add(t, r23, p1b);
            t.f.x = fmaxf(t.f.x, 0.0f); t.f.y = fmaxf(t.f.y, 0.0f);
            pk_fma(acc[1][jj], t, v23, acc[1][jj]);
        }
    }

    __syncthreads();   // all warps done reading Psh before red overwrites it

#pragma unroll
    for (int ii = 0; ii < 2; ii++)
#pragma unroll
        for (int jj = 0; jj < 4; jj++) {
            int i = ilane + 8 * ii;
            int j = jlane + 4 * jj;
            red[hq * 264 + i * 16 + j] = acc[ii][jj].f.x + acc[ii][jj].f.y;
        }
    __syncthreads();

#pragma unroll
    for (int rep = 0; rep < 2; rep++) {
        int idx = tid + rep * 128;
        int i = idx >> 4, j = idx & 15;
        int o = i * 16 + j;
        float s = red[o] + red[264 + o] + red[528 + o] + red[792 + o];
        float d = cej[rep] - cei[rep]; if (d <= 1e-6f) d = 100.0f;
        int gi = i0 + i, gj = j0 + j;
        out[((size_t)(b * SS + gi) * SS + gj) * CC + c] = __fdividef(s, d) + vb;
    }
}

// ---------------------------------------------------------------------------
extern "C" void kernel_launch(void* const* d_in, const int* in_sizes, int n_in,
                              void* d_out, int out_size)
{
    (void)in_sizes; (void)n_in; (void)out_size;
    const float* memory = (const float*)d_in[0];
    const float* Ww     = (const float*)d_in[1];
    const float* Wb     = (const float*)d_in[2];
    const float* Uw     = (const float*)d_in[3];
    const float* Vw     = (const float*)d_in[4];
    const float* Vb     = (const float*)d_in[5];
    float* out          = (float*)d_out;

    kernelA<<<256, 256>>>(memory, Ww, Wb, Uw);
    kernelB<<<128, 256>>>(memory);
    kernelMain<<<1024, 128>>>(Vw, Vb, out);
}